// round 1
// baseline (speedup 1.0000x reference)
#include <cuda_runtime.h>
#include <math.h>

#define BB   4
#define NATN 1024
#define JJN  200

// scratch: DR descriptors (B*NAT, 1600) and type-sorted atom list
__device__ float g_DR[(size_t)BB * NATN * 1600];
__device__ int   g_sorted_n[1032];

// ---------------------------------------------------------------------------
// Kernel 0: deterministic partition of n-indices by atom type (single block)
// ---------------------------------------------------------------------------
__global__ void sort_kernel(const int* __restrict__ tmap)
{
    __shared__ int sa[1024], sb[1024];
    int tid = threadIdx.x;
    int myt = tmap[tid];
    sa[tid] = (myt == 0) ? 1 : 0;
    __syncthreads();
    int* cur = sa; int* nxt = sb;
    for (int off = 1; off < 1024; off <<= 1) {
        int v = cur[tid];
        if (tid >= off) v += cur[tid - off];
        __syncthreads();
        nxt[tid] = v;
        __syncthreads();
        int* tpp = cur; cur = nxt; nxt = tpp;
    }
    int scan0 = cur[tid];      // inclusive count of type-0 up to tid
    int cnt0  = cur[1023];

    g_sorted_n[tid] = -1;
    if (tid < 8) g_sorted_n[1024 + tid] = -1;
    __syncthreads();

    if (myt == 0) {
        g_sorted_n[scan0 - 1] = tid;
    } else {
        int base1 = ((cnt0 + 3) >> 2) << 2;   // 4-aligned so fit blocks are type-uniform
        g_sorted_n[base1 + tid - scan0] = tid;
    }
}

// ---------------------------------------------------------------------------
// Kernel 1: embedding net + xyz contraction + DR descriptor. One block = atom.
// ---------------------------------------------------------------------------
__global__ void __launch_bounds__(256, 1) embed_kernel(
    const float4* __restrict__ imdr,      // (B*NAT*200) float4 (r, r*dx, r*dy, r*dz)
    const int*    __restrict__ tmap,      // (NAT)
    const float4* __restrict__ davg,      // (2*200) float4
    const float4* __restrict__ dstd,
    const float*  __restrict__ type_vector, // (2,4)
    const float*  __restrict__ tW0, const float* __restrict__ tb0,   // (4,8),(8)
    const float*  __restrict__ eW0, const float* __restrict__ eb0,   // (9,25),(25)
    const float*  __restrict__ eW1, const float* __restrict__ eb1,   // (25,50),(50)
    const float*  __restrict__ eW2, const float* __restrict__ eb2)   // (50,100),(100)
{
    extern __shared__ float sm[];
    float* sW0  = sm;             // 225
    float* sB0  = sW0 + 225;      // 25
    float* sW1  = sB0 + 25;       // 1250
    float* sB1  = sW1 + 1250;     // 50
    float* sW2  = sB1 + 50;       // 5000   (8B-aligned offset: 1550*4 = 6200)
    float* sB2  = sW2 + 5000;     // 100
    float* sRi  = sB2 + 100;      // 200*4
    float* sG   = sRi + 800;      // 200*51 (stride 51 -> conflict-free)
    float* sXYZ = sG + 10200;     // 4*100
    // total 18050 floats = 72200 B

    int tid = threadIdx.x;
    int a = blockIdx.x;
    int n = a & 1023;
    int t = tmap[n];

    for (int i = tid; i < 225;  i += 256) sW0[i] = eW0[i];
    for (int i = tid; i < 25;   i += 256) sB0[i] = eb0[i];
    for (int i = tid; i < 1250; i += 256) sW1[i] = eW1[i];
    for (int i = tid; i < 50;   i += 256) sB1[i] = eb1[i];
    for (int i = tid; i < 5000; i += 256) sW2[i] = eW2[i];
    for (int i = tid; i < 100;  i += 256) sB2[i] = eb2[i];

    bool act = (tid < 200);
    float h1[50];

    if (act) {
        int j = tid;
        float4 im = imdr[(size_t)a * 200 + j];
        float r = im.x;
        float invr = (r > 1e-5f) ? (1.0f / r) : 1.0f;
        float u  = (r - 0.5f) * (1.0f / 5.5f);
        float u2 = u * u;
        float smid = invr * (u * u2 * (-6.0f * u2 + 15.0f * u - 10.0f) + 1.0f);
        float srij = 0.0f;
        if (r > 0.0f && r < 0.5f)        srij = invr;
        else if (r >= 0.5f && r < 6.0f)  srij = smid;
        bool msk = fabsf(r) > 1e-5f;
        float ri0 = srij;
        float ri1 = msk ? srij * im.y * invr : 0.0f;
        float ri2 = msk ? srij * im.z * invr : 0.0f;
        float ri3 = msk ? srij * im.w * invr : 0.0f;
        float4 da = davg[t * 200 + j];
        float4 ds = dstd[t * 200 + j];
        ri0 = (ri0 - da.x) / ds.x;
        ri1 = (ri1 - da.y) / ds.y;
        ri2 = (ri2 - da.z) / ds.z;
        ri3 = (ri3 - da.w) / ds.w;
        sRi[j * 4 + 0] = ri0; sRi[j * 4 + 1] = ri1;
        sRi[j * 4 + 2] = ri2; sRi[j * 4 + 3] = ri3;

        // neighbor-type feature: tanh(tv @ tW0 + tb0) + concat[tv, tv]
        int nt = (j >= 100) ? 1 : 0;
        float tv[4];
        tv[0] = type_vector[nt * 4 + 0];
        tv[1] = type_vector[nt * 4 + 1];
        tv[2] = type_vector[nt * 4 + 2];
        tv[3] = type_vector[nt * 4 + 3];
        float nf[8];
        #pragma unroll
        for (int i2 = 0; i2 < 8; i2++) {
            float acc = tb0[i2];
            #pragma unroll
            for (int p = 0; p < 4; p++) acc += tv[p] * tW0[p * 8 + i2];
            nf[i2] = tanhf(acc) + tv[i2 & 3];
        }

        // layer0: x=[ri0, nf(8)] -> 25 (no resnet)
        float h0[25];
        #pragma unroll
        for (int m = 0; m < 25; m++) h0[m] = sB0[m] + ri0 * sW0[m];
        #pragma unroll
        for (int k = 0; k < 8; k++) {
            float xk = nf[k];
            #pragma unroll
            for (int m = 0; m < 25; m++) h0[m] += xk * sW0[(k + 1) * 25 + m];
        }
        #pragma unroll
        for (int m = 0; m < 25; m++) h0[m] = tanhf(h0[m]);

        // layer1: 25 -> 50, resnet += concat[h0,h0]
        #pragma unroll
        for (int m = 0; m < 50; m++) h1[m] = sB1[m];
        for (int k = 0; k < 25; k++) {
            float hk = h0[k];
            #pragma unroll
            for (int m = 0; m < 50; m++) h1[m] += hk * sW1[k * 50 + m];
        }
        #pragma unroll
        for (int m = 0; m < 50; m++)
            h1[m] = tanhf(h1[m]) + h0[(m < 25) ? m : (m - 25)];
    }
    __syncthreads();

    // layer2 (50 -> 100, resnet += concat[h1,h1]) in two 50-wide chunks,
    // interleaved with the xyz reduction to bound shared usage.
    for (int c = 0; c < 2; c++) {
        if (act) {
            int j = tid;
            float acc[50];
            #pragma unroll
            for (int m = 0; m < 50; m++) acc[m] = sB2[c * 50 + m];
            const float2* w2 = (const float2*)sW2;
            for (int k = 0; k < 50; k++) {
                float hk = h1[k];
                int base = k * 50 + c * 25;
                #pragma unroll
                for (int mm = 0; mm < 25; mm++) {
                    float2 w = w2[base + mm];
                    acc[2 * mm]     += hk * w.x;
                    acc[2 * mm + 1] += hk * w.y;
                }
            }
            #pragma unroll
            for (int m = 0; m < 50; m++)
                sG[j * 51 + m] = tanhf(acc[m]) + h1[m];
        }
        __syncthreads();
        if (tid < 200) {
            int d = tid / 50, mq = tid % 50;
            float s = 0.0f;
            #pragma unroll 4
            for (int jj = 0; jj < 200; jj++)
                s += sRi[jj * 4 + d] * sG[jj * 51 + mq];
            sXYZ[d * 100 + c * 50 + mq] = s * (1.0f / 200.0f);
        }
        __syncthreads();
    }

    // DR[m][q] = sum_d xyz[d][m] * xyz[d][q], q < 16
    for (int idx = tid; idx < 1600; idx += 256) {
        int m = idx >> 4, q = idx & 15;
        float s = 0.0f;
        #pragma unroll
        for (int d = 0; d < 4; d++)
            s += sXYZ[d * 100 + m] * sXYZ[d * 100 + q];
        g_DR[(size_t)a * 1600 + idx] = s;
    }
}

// ---------------------------------------------------------------------------
// Kernel 2: fitting net. Block = 4 same-type n's x 4 batches = 16 rows.
// ---------------------------------------------------------------------------
__global__ void __launch_bounds__(256, 1) fit_kernel(
    const int*   __restrict__ tmap,
    const float* __restrict__ fW0, const float* __restrict__ fb0,
    const float* __restrict__ fW1, const float* __restrict__ fb1,
    const float* __restrict__ fW2, const float* __restrict__ fb2,
    const float* __restrict__ fWf, const float* __restrict__ fbf,
    float* __restrict__ out)
{
    extern __shared__ float sm[];
    float* sDR = sm;            // 16*1600
    float* sHa = sDR + 25600;   // 16*240
    float* sHb = sHa + 3840;    // 16*240
    // 33280 floats = 133120 B

    int tid = threadIdx.x;
    int g = blockIdx.x;
    int nn[4];
    nn[0] = g_sorted_n[g * 4 + 0];
    nn[1] = g_sorted_n[g * 4 + 1];
    nn[2] = g_sorted_n[g * 4 + 2];
    nn[3] = g_sorted_n[g * 4 + 3];
    int firstn = (nn[0] >= 0) ? nn[0] : (nn[1] >= 0) ? nn[1]
               : (nn[2] >= 0) ? nn[2] : nn[3];
    if (firstn < 0) return;     // uniform: all-empty padding block
    int t = tmap[firstn];

    for (int idx = tid; idx < 16 * 1600; idx += 256) {
        int row = idx / 1600;
        int k   = idx - row * 1600;
        int b   = row >> 2, s = row & 3;
        int nv  = nn[s];
        sDR[idx] = (nv >= 0) ? g_DR[((size_t)(b * 1024 + nv)) * 1600 + k] : 0.0f;
    }
    __syncthreads();

    int m = tid;
    float acc[16];
    const float* W0 = fW0 + (size_t)t * 1600 * 240;
    const float* W1 = fW1 + t * 240 * 240;
    const float* W2 = fW2 + t * 240 * 240;

    // layer0: 1600 -> 240, no resnet
    if (m < 240) {
        float b0v = fb0[t * 240 + m];
        #pragma unroll
        for (int i = 0; i < 16; i++) acc[i] = b0v;
        for (int k = 0; k < 1600; k += 4) {
            float w0 = W0[(k + 0) * 240 + m];
            float w1 = W0[(k + 1) * 240 + m];
            float w2v = W0[(k + 2) * 240 + m];
            float w3 = W0[(k + 3) * 240 + m];
            #pragma unroll
            for (int i = 0; i < 16; i++) {
                float4 d4 = *(const float4*)&sDR[i * 1600 + k];
                acc[i] += d4.x * w0 + d4.y * w1 + d4.z * w2v + d4.w * w3;
            }
        }
        #pragma unroll
        for (int i = 0; i < 16; i++) sHa[i * 240 + m] = tanhf(acc[i]);
    }
    __syncthreads();

    // layer1: 240 -> 240, resnet
    if (m < 240) {
        float b1v = fb1[t * 240 + m];
        #pragma unroll
        for (int i = 0; i < 16; i++) acc[i] = b1v;
        for (int k = 0; k < 240; k += 4) {
            float w0 = W1[(k + 0) * 240 + m];
            float w1 = W1[(k + 1) * 240 + m];
            float w2v = W1[(k + 2) * 240 + m];
            float w3 = W1[(k + 3) * 240 + m];
            #pragma unroll
            for (int i = 0; i < 16; i++) {
                float4 h4 = *(const float4*)&sHa[i * 240 + k];
                acc[i] += h4.x * w0 + h4.y * w1 + h4.z * w2v + h4.w * w3;
            }
        }
        #pragma unroll
        for (int i = 0; i < 16; i++)
            sHb[i * 240 + m] = tanhf(acc[i]) + sHa[i * 240 + m];
    }
    __syncthreads();

    // layer2: 240 -> 240, resnet (writes back into sHa; reads of sHa are done)
    if (m < 240) {
        float b2v = fb2[t * 240 + m];
        #pragma unroll
        for (int i = 0; i < 16; i++) acc[i] = b2v;
        for (int k = 0; k < 240; k += 4) {
            float w0 = W2[(k + 0) * 240 + m];
            float w1 = W2[(k + 1) * 240 + m];
            float w2v = W2[(k + 2) * 240 + m];
            float w3 = W2[(k + 3) * 240 + m];
            #pragma unroll
            for (int i = 0; i < 16; i++) {
                float4 h4 = *(const float4*)&sHb[i * 240 + k];
                acc[i] += h4.x * w0 + h4.y * w1 + h4.z * w2v + h4.w * w3;
            }
        }
        #pragma unroll
        for (int i = 0; i < 16; i++)
            sHa[i * 240 + m] = tanhf(acc[i]) + sHb[i * 240 + m];
    }
    __syncthreads();

    // final: h @ fWf + fbf
    if (tid < 16) {
        int i = tid, b = i >> 2, s = i & 3;
        int nv = nn[s];
        if (nv >= 0) {
            float e = fbf[t];
            const float* Wf = fWf + t * 240;
            float s0 = 0.0f;
            for (int k = 0; k < 240; k++) s0 += sHa[i * 240 + k] * Wf[k];
            out[4 + b * 1024 + nv] = e + s0;
        }
    }
}

// ---------------------------------------------------------------------------
// Kernel 3: Etot = sum_n Ei (deterministic tree reduce, one block per batch)
// ---------------------------------------------------------------------------
__global__ void etot_kernel(float* __restrict__ out)
{
    __shared__ float red[256];
    int b = blockIdx.x, tid = threadIdx.x;
    float s = 0.0f;
    for (int i = tid; i < 1024; i += 256) s += out[4 + b * 1024 + i];
    red[tid] = s;
    __syncthreads();
    for (int off = 128; off > 0; off >>= 1) {
        if (tid < off) red[tid] += red[tid + off];
        __syncthreads();
    }
    if (tid == 0) out[b] = red[0];
}

// ---------------------------------------------------------------------------
extern "C" void kernel_launch(void* const* d_in, const int* in_sizes, int n_in,
                              void* d_out, int out_size)
{
    // input order: list_neigh, Imagetype_map, type_map, ImageDR, [nghost],
    //              davg, dstd, type_vector, tW0, tb0, eW0, eb0, eW1, eb1,
    //              eW2, eb2, fW0, fb0, fW1, fb1, fW2, fb2, fWf, fbf
    int off = (n_in >= 24) ? 0 : -1;   // nghost scalar may or may not materialize

    const int*    tmap = (const int*)   d_in[1];
    const float4* imdr = (const float4*)d_in[3];
    const float4* davg = (const float4*)d_in[5 + off];
    const float4* dstd = (const float4*)d_in[6 + off];
    const float*  tvec = (const float*) d_in[7 + off];
    const float*  tW0  = (const float*) d_in[8 + off];
    const float*  tb0  = (const float*) d_in[9 + off];
    const float*  eW0  = (const float*) d_in[10 + off];
    const float*  eb0  = (const float*) d_in[11 + off];
    const float*  eW1  = (const float*) d_in[12 + off];
    const float*  eb1  = (const float*) d_in[13 + off];
    const float*  eW2  = (const float*) d_in[14 + off];
    const float*  eb2  = (const float*) d_in[15 + off];
    const float*  fW0  = (const float*) d_in[16 + off];
    const float*  fb0  = (const float*) d_in[17 + off];
    const float*  fW1  = (const float*) d_in[18 + off];
    const float*  fb1  = (const float*) d_in[19 + off];
    const float*  fW2  = (const float*) d_in[20 + off];
    const float*  fb2  = (const float*) d_in[21 + off];
    const float*  fWf  = (const float*) d_in[22 + off];
    const float*  fbf  = (const float*) d_in[23 + off];
    float* out = (float*)d_out;

    cudaFuncSetAttribute(embed_kernel, cudaFuncAttributeMaxDynamicSharedMemorySize, 72200);
    cudaFuncSetAttribute(fit_kernel,   cudaFuncAttributeMaxDynamicSharedMemorySize, 133120);

    sort_kernel<<<1, 1024>>>(tmap);
    embed_kernel<<<4096, 256, 72200>>>(imdr, tmap, davg, dstd, tvec,
                                       tW0, tb0, eW0, eb0, eW1, eb1, eW2, eb2);
    fit_kernel<<<258, 256, 133120>>>(tmap, fW0, fb0, fW1, fb1, fW2, fb2,
                                     fWf, fbf, out);
    etot_kernel<<<4, 256>>>(out);
}

// round 2
// speedup vs baseline: 1.0318x; 1.0318x over previous
#include <cuda_runtime.h>
#include <math.h>

#define BB   4
#define NATN 1024
#define JJN  200

// scratch: DR descriptors (B*NAT, 1600) and type-sorted atom list
__device__ float g_DR[(size_t)BB * NATN * 1600];
__device__ int   g_sorted_n[1032];

// Branch-free fast tanh: rel err ~1e-6, no overflow for any x.
__device__ __forceinline__ float fast_tanh(float x)
{
    float a = fabsf(x);
    float t = __expf(-2.0f * a);              // MUFU.EX2 path, t in (0,1]
    float r = __fdividef(1.0f - t, 1.0f + t); // MUFU.RCP-based divide
    return copysignf(r, x);
}

// ---------------------------------------------------------------------------
// Kernel 0: deterministic partition of n-indices by atom type (single block)
// ---------------------------------------------------------------------------
__global__ void sort_kernel(const int* __restrict__ tmap)
{
    __shared__ int sa[1024], sb[1024];
    int tid = threadIdx.x;
    int myt = tmap[tid];
    sa[tid] = (myt == 0) ? 1 : 0;
    __syncthreads();
    int* cur = sa; int* nxt = sb;
    for (int off = 1; off < 1024; off <<= 1) {
        int v = cur[tid];
        if (tid >= off) v += cur[tid - off];
        __syncthreads();
        nxt[tid] = v;
        __syncthreads();
        int* tpp = cur; cur = nxt; nxt = tpp;
    }
    int scan0 = cur[tid];      // inclusive count of type-0 up to tid
    int cnt0  = cur[1023];

    g_sorted_n[tid] = -1;
    if (tid < 8) g_sorted_n[1024 + tid] = -1;
    __syncthreads();

    if (myt == 0) {
        g_sorted_n[scan0 - 1] = tid;
    } else {
        int base1 = ((cnt0 + 3) >> 2) << 2;   // 4-aligned so fit blocks are type-uniform
        g_sorted_n[base1 + tid - scan0] = tid;
    }
}

// ---------------------------------------------------------------------------
// Kernel 1: embedding net + xyz contraction + DR descriptor. One block = atom.
// ---------------------------------------------------------------------------
__global__ void __launch_bounds__(256, 1) embed_kernel(
    const float4* __restrict__ imdr,      // (B*NAT*200) float4 (r, r*dx, r*dy, r*dz)
    const int*    __restrict__ tmap,      // (NAT)
    const float4* __restrict__ davg,      // (2*200) float4
    const float4* __restrict__ dstd,
    const float*  __restrict__ type_vector, // (2,4)
    const float*  __restrict__ tW0, const float* __restrict__ tb0,   // (4,8),(8)
    const float*  __restrict__ eW0, const float* __restrict__ eb0,   // (9,25),(25)
    const float*  __restrict__ eW1, const float* __restrict__ eb1,   // (25,50),(50)
    const float*  __restrict__ eW2, const float* __restrict__ eb2)   // (50,100),(100)
{
    extern __shared__ float sm[];
    float* sW0  = sm;             // 225
    float* sB0  = sW0 + 225;      // 25
    float* sW1  = sB0 + 25;       // 1250
    float* sB1  = sW1 + 1250;     // 50
    float* sW2  = sB1 + 50;       // 5000   (8B-aligned offset: 1550*4 = 6200)
    float* sB2  = sW2 + 5000;     // 100
    float* sBias= sB2 + 100;      // 50 : per-type folded layer0 bias (2 x 25)
    float* sRi  = sBias + 50;     // 200*4
    float* sG   = sRi + 800;      // 200*51 (stride 51 -> conflict-free)
    float* sXYZ = sG + 10200;     // 4*100
    // total 18100 floats = 72400 B

    int tid = threadIdx.x;
    int a = blockIdx.x;
    int n = a & 1023;
    int t = tmap[n];

    for (int i = tid; i < 225;  i += 256) sW0[i] = eW0[i];
    for (int i = tid; i < 25;   i += 256) sB0[i] = eb0[i];
    for (int i = tid; i < 1250; i += 256) sW1[i] = eW1[i];
    for (int i = tid; i < 50;   i += 256) sB1[i] = eb1[i];
    for (int i = tid; i < 5000; i += 256) sW2[i] = eW2[i];
    for (int i = tid; i < 100;  i += 256) sB2[i] = eb2[i];
    __syncthreads();

    // Fold neighbor-type feature into a per-type layer0 bias:
    // nf_t[k] = tanh(tv_t @ tW0 + tb0)[k] + tv_t[k&3]
    // sBias[t][m] = eb0[m] + sum_k nf_t[k] * eW0[(1+k),m]
    if (tid < 50) {
        int tt = tid / 25, m = tid % 25;
        float tv[4];
        #pragma unroll
        for (int p = 0; p < 4; p++) tv[p] = type_vector[tt * 4 + p];
        float bias = sB0[m];
        #pragma unroll
        for (int k = 0; k < 8; k++) {
            float acc = tb0[k];
            #pragma unroll
            for (int p = 0; p < 4; p++) acc += tv[p] * tW0[p * 8 + k];
            float nfk = fast_tanh(acc) + tv[k & 3];
            bias += nfk * sW0[(k + 1) * 25 + m];
        }
        sBias[tt * 25 + m] = bias;
    }

    bool act = (tid < 200);
    float h1[50];
    float ri0 = 0.0f;
    int   nt  = 0;

    if (act) {
        int j = tid;
        nt = (j >= 100) ? 1 : 0;
        float4 im = imdr[(size_t)a * 200 + j];
        float r = im.x;
        float invr = (r > 1e-5f) ? (1.0f / r) : 1.0f;
        float u  = (r - 0.5f) * (1.0f / 5.5f);
        float u2 = u * u;
        float smid = invr * (u * u2 * (-6.0f * u2 + 15.0f * u - 10.0f) + 1.0f);
        float srij = 0.0f;
        if (r > 0.0f && r < 0.5f)        srij = invr;
        else if (r >= 0.5f && r < 6.0f)  srij = smid;
        bool msk = fabsf(r) > 1e-5f;
        float v0 = srij;
        float v1 = msk ? srij * im.y * invr : 0.0f;
        float v2 = msk ? srij * im.z * invr : 0.0f;
        float v3 = msk ? srij * im.w * invr : 0.0f;
        float4 da = davg[t * 200 + j];
        float4 ds = dstd[t * 200 + j];
        v0 = (v0 - da.x) / ds.x;
        v1 = (v1 - da.y) / ds.y;
        v2 = (v2 - da.z) / ds.z;
        v3 = (v3 - da.w) / ds.w;
        sRi[j * 4 + 0] = v0; sRi[j * 4 + 1] = v1;
        sRi[j * 4 + 2] = v2; sRi[j * 4 + 3] = v3;
        ri0 = v0;
    }
    __syncthreads();

    if (act) {
        // layer0: x=[ri0, nf] -> 25 via folded bias (no resnet)
        float h0[25];
        #pragma unroll
        for (int m = 0; m < 25; m++)
            h0[m] = fast_tanh(sBias[nt * 25 + m] + ri0 * sW0[m]);

        // layer1: 25 -> 50, resnet += concat[h0,h0]
        #pragma unroll
        for (int m = 0; m < 50; m++) h1[m] = sB1[m];
        for (int k = 0; k < 25; k++) {
            float hk = h0[k];
            #pragma unroll
            for (int m = 0; m < 50; m++) h1[m] += hk * sW1[k * 50 + m];
        }
        #pragma unroll
        for (int m = 0; m < 50; m++)
            h1[m] = fast_tanh(h1[m]) + h0[(m < 25) ? m : (m - 25)];
    }

    // layer2 (50 -> 100, resnet += concat[h1,h1]) in two 50-wide chunks,
    // interleaved with the xyz reduction to bound shared usage.
    for (int c = 0; c < 2; c++) {
        if (act) {
            int j = tid;
            float acc[50];
            #pragma unroll
            for (int m = 0; m < 50; m++) acc[m] = sB2[c * 50 + m];
            const float2* w2 = (const float2*)sW2;
            for (int k = 0; k < 50; k++) {
                float hk = h1[k];
                int base = k * 50 + c * 25;
                #pragma unroll
                for (int mm = 0; mm < 25; mm++) {
                    float2 w = w2[base + mm];
                    acc[2 * mm]     += hk * w.x;
                    acc[2 * mm + 1] += hk * w.y;
                }
            }
            #pragma unroll
            for (int m = 0; m < 50; m++)
                sG[j * 51 + m] = fast_tanh(acc[m]) + h1[m];
        }
        __syncthreads();
        if (tid < 200) {
            int d = tid / 50, mq = tid % 50;
            float s = 0.0f;
            #pragma unroll 4
            for (int jj = 0; jj < 200; jj++)
                s += sRi[jj * 4 + d] * sG[jj * 51 + mq];
            sXYZ[d * 100 + c * 50 + mq] = s * (1.0f / 200.0f);
        }
        __syncthreads();
    }

    // DR[m][q] = sum_d xyz[d][m] * xyz[d][q], q < 16
    for (int idx = tid; idx < 1600; idx += 256) {
        int m = idx >> 4, q = idx & 15;
        float s = 0.0f;
        #pragma unroll
        for (int d = 0; d < 4; d++)
            s += sXYZ[d * 100 + m] * sXYZ[d * 100 + q];
        g_DR[(size_t)a * 1600 + idx] = s;
    }
}

// ---------------------------------------------------------------------------
// Kernel 2: fitting net. Block = 4 same-type n's x 4 batches = 16 rows.
// ---------------------------------------------------------------------------
__global__ void __launch_bounds__(256, 1) fit_kernel(
    const int*   __restrict__ tmap,
    const float* __restrict__ fW0, const float* __restrict__ fb0,
    const float* __restrict__ fW1, const float* __restrict__ fb1,
    const float* __restrict__ fW2, const float* __restrict__ fb2,
    const float* __restrict__ fWf, const float* __restrict__ fbf,
    float* __restrict__ out)
{
    extern __shared__ float sm[];
    float* sDR = sm;            // 16*1600
    float* sHa = sDR + 25600;   // 16*240
    float* sHb = sHa + 3840;    // 16*240
    // 33280 floats = 133120 B

    int tid = threadIdx.x;
    int g = blockIdx.x;
    int nn[4];
    nn[0] = g_sorted_n[g * 4 + 0];
    nn[1] = g_sorted_n[g * 4 + 1];
    nn[2] = g_sorted_n[g * 4 + 2];
    nn[3] = g_sorted_n[g * 4 + 3];
    int firstn = (nn[0] >= 0) ? nn[0] : (nn[1] >= 0) ? nn[1]
               : (nn[2] >= 0) ? nn[2] : nn[3];
    if (firstn < 0) return;     // uniform: all-empty padding block
    int t = tmap[firstn];

    for (int idx = tid; idx < 16 * 1600; idx += 256) {
        int row = idx / 1600;
        int k   = idx - row * 1600;
        int b   = row >> 2, s = row & 3;
        int nv  = nn[s];
        sDR[idx] = (nv >= 0) ? g_DR[((size_t)(b * 1024 + nv)) * 1600 + k] : 0.0f;
    }
    __syncthreads();

    int m = tid;
    float acc[16];
    const float* W0 = fW0 + (size_t)t * 1600 * 240;
    const float* W1 = fW1 + t * 240 * 240;
    const float* W2 = fW2 + t * 240 * 240;

    // layer0: 1600 -> 240, no resnet
    if (m < 240) {
        float b0v = fb0[t * 240 + m];
        #pragma unroll
        for (int i = 0; i < 16; i++) acc[i] = b0v;
        for (int k = 0; k < 1600; k += 4) {
            float w0 = W0[(k + 0) * 240 + m];
            float w1 = W0[(k + 1) * 240 + m];
            float w2v = W0[(k + 2) * 240 + m];
            float w3 = W0[(k + 3) * 240 + m];
            #pragma unroll
            for (int i = 0; i < 16; i++) {
                float4 d4 = *(const float4*)&sDR[i * 1600 + k];
                acc[i] += d4.x * w0 + d4.y * w1 + d4.z * w2v + d4.w * w3;
            }
        }
        #pragma unroll
        for (int i = 0; i < 16; i++) sHa[i * 240 + m] = fast_tanh(acc[i]);
    }
    __syncthreads();

    // layer1: 240 -> 240, resnet
    if (m < 240) {
        float b1v = fb1[t * 240 + m];
        #pragma unroll
        for (int i = 0; i < 16; i++) acc[i] = b1v;
        for (int k = 0; k < 240; k += 4) {
            float w0 = W1[(k + 0) * 240 + m];
            float w1 = W1[(k + 1) * 240 + m];
            float w2v = W1[(k + 2) * 240 + m];
            float w3 = W1[(k + 3) * 240 + m];
            #pragma unroll
            for (int i = 0; i < 16; i++) {
                float4 h4 = *(const float4*)&sHa[i * 240 + k];
                acc[i] += h4.x * w0 + h4.y * w1 + h4.z * w2v + h4.w * w3;
            }
        }
        #pragma unroll
        for (int i = 0; i < 16; i++)
            sHb[i * 240 + m] = fast_tanh(acc[i]) + sHa[i * 240 + m];
    }
    __syncthreads();

    // layer2: 240 -> 240, resnet (writes back into sHa; reads of sHa are done)
    if (m < 240) {
        float b2v = fb2[t * 240 + m];
        #pragma unroll
        for (int i = 0; i < 16; i++) acc[i] = b2v;
        for (int k = 0; k < 240; k += 4) {
            float w0 = W2[(k + 0) * 240 + m];
            float w1 = W2[(k + 1) * 240 + m];
            float w2v = W2[(k + 2) * 240 + m];
            float w3 = W2[(k + 3) * 240 + m];
            #pragma unroll
            for (int i = 0; i < 16; i++) {
                float4 h4 = *(const float4*)&sHb[i * 240 + k];
                acc[i] += h4.x * w0 + h4.y * w1 + h4.z * w2v + h4.w * w3;
            }
        }
        #pragma unroll
        for (int i = 0; i < 16; i++)
            sHa[i * 240 + m] = fast_tanh(acc[i]) + sHb[i * 240 + m];
    }
    __syncthreads();

    // final: h @ fWf + fbf
    if (tid < 16) {
        int i = tid, b = i >> 2, s = i & 3;
        int nv = nn[s];
        if (nv >= 0) {
            float e = fbf[t];
            const float* Wf = fWf + t * 240;
            float s0 = 0.0f;
            for (int k = 0; k < 240; k++) s0 += sHa[i * 240 + k] * Wf[k];
            out[4 + b * 1024 + nv] = e + s0;
        }
    }
}

// ---------------------------------------------------------------------------
// Kernel 3: Etot = sum_n Ei (deterministic tree reduce, one block per batch)
// ---------------------------------------------------------------------------
__global__ void etot_kernel(float* __restrict__ out)
{
    __shared__ float red[256];
    int b = blockIdx.x, tid = threadIdx.x;
    float s = 0.0f;
    for (int i = tid; i < 1024; i += 256) s += out[4 + b * 1024 + i];
    red[tid] = s;
    __syncthreads();
    for (int off = 128; off > 0; off >>= 1) {
        if (tid < off) red[tid] += red[tid + off];
        __syncthreads();
    }
    if (tid == 0) out[b] = red[0];
}

// ---------------------------------------------------------------------------
extern "C" void kernel_launch(void* const* d_in, const int* in_sizes, int n_in,
                              void* d_out, int out_size)
{
    // input order: list_neigh, Imagetype_map, type_map, ImageDR, [nghost],
    //              davg, dstd, type_vector, tW0, tb0, eW0, eb0, eW1, eb1,
    //              eW2, eb2, fW0, fb0, fW1, fb1, fW2, fb2, fWf, fbf
    int off = (n_in >= 24) ? 0 : -1;   // nghost scalar may or may not materialize

    const int*    tmap = (const int*)   d_in[1];
    const float4* imdr = (const float4*)d_in[3];
    const float4* davg = (const float4*)d_in[5 + off];
    const float4* dstd = (const float4*)d_in[6 + off];
    const float*  tvec = (const float*) d_in[7 + off];
    const float*  tW0  = (const float*) d_in[8 + off];
    const float*  tb0  = (const float*) d_in[9 + off];
    const float*  eW0  = (const float*) d_in[10 + off];
    const float*  eb0  = (const float*) d_in[11 + off];
    const float*  eW1  = (const float*) d_in[12 + off];
    const float*  eb1  = (const float*) d_in[13 + off];
    const float*  eW2  = (const float*) d_in[14 + off];
    const float*  eb2  = (const float*) d_in[15 + off];
    const float*  fW0  = (const float*) d_in[16 + off];
    const float*  fb0  = (const float*) d_in[17 + off];
    const float*  fW1  = (const float*) d_in[18 + off];
    const float*  fb1  = (const float*) d_in[19 + off];
    const float*  fW2  = (const float*) d_in[20 + off];
    const float*  fb2  = (const float*) d_in[21 + off];
    const float*  fWf  = (const float*) d_in[22 + off];
    const float*  fbf  = (const float*) d_in[23 + off];
    float* out = (float*)d_out;

    cudaFuncSetAttribute(embed_kernel, cudaFuncAttributeMaxDynamicSharedMemorySize, 72400);
    cudaFuncSetAttribute(fit_kernel,   cudaFuncAttributeMaxDynamicSharedMemorySize, 133120);

    sort_kernel<<<1, 1024>>>(tmap);
    embed_kernel<<<4096, 256, 72400>>>(imdr, tmap, davg, dstd, tvec,
                                       tW0, tb0, eW0, eb0, eW1, eb1, eW2, eb2);
    fit_kernel<<<258, 256, 133120>>>(tmap, fW0, fb0, fW1, fb1, fW2, fb2,
                                     fWf, fbf, out);
    etot_kernel<<<4, 256>>>(out);
}

// round 3
// speedup vs baseline: 1.1283x; 1.0935x over previous
#include <cuda_runtime.h>
#include <math.h>

#define BB   4
#define NATN 1024
#define JJN  200

// scratch: DR descriptors (B*NAT, 1600) and type-sorted atom list
__device__ float g_DR[(size_t)BB * NATN * 1600];
__device__ int   g_sorted_n[1032];

// Branch-free fast tanh: rel err ~1e-6, no overflow for any x.
__device__ __forceinline__ float fast_tanh(float x)
{
    float a = fabsf(x);
    float t = __expf(-2.0f * a);              // MUFU.EX2 path, t in (0,1]
    float r = __fdividef(1.0f - t, 1.0f + t); // MUFU.RCP-based divide
    return copysignf(r, x);
}

// ---------------------------------------------------------------------------
// Kernel 0: deterministic partition of n-indices by atom type (single block)
// ---------------------------------------------------------------------------
__global__ void sort_kernel(const int* __restrict__ tmap)
{
    __shared__ int sa[1024], sb[1024];
    int tid = threadIdx.x;
    int myt = tmap[tid];
    sa[tid] = (myt == 0) ? 1 : 0;
    __syncthreads();
    int* cur = sa; int* nxt = sb;
    for (int off = 1; off < 1024; off <<= 1) {
        int v = cur[tid];
        if (tid >= off) v += cur[tid - off];
        __syncthreads();
        nxt[tid] = v;
        __syncthreads();
        int* tpp = cur; cur = nxt; nxt = tpp;
    }
    int scan0 = cur[tid];      // inclusive count of type-0 up to tid
    int cnt0  = cur[1023];

    g_sorted_n[tid] = -1;
    if (tid < 8) g_sorted_n[1024 + tid] = -1;
    __syncthreads();

    if (myt == 0) {
        g_sorted_n[scan0 - 1] = tid;
    } else {
        int base1 = ((cnt0 + 3) >> 2) << 2;   // 4-aligned so fit blocks are type-uniform
        g_sorted_n[base1 + tid - scan0] = tid;
    }
}

// ---------------------------------------------------------------------------
// Kernel 1: embedding net + xyz contraction + DR descriptor. One block = atom.
// Shared layout (floats, all offsets multiple of 4 for LDS.128):
//   sW0   [0,228)        eW0 (9x25) row-major, 225 used
//   sB0   [228,256)      eb0 (25)
//   sW1p  [256,1556)     eW1 padded rows: 25 x 52 (50 used)
//   sB1   [1556,1608)    eb1 (50)
//   sW2p  [1608,7208)    eW2 repacked: 50 rows x (4 chunks x 28), 25 used/chunk
//   sB2   [7208,7308)    eb2 (100)
//   sBias [7308,7360)    folded per-type layer0 bias (2 x 25)
//   sRiT  [7360,8176)    Ri transposed: 4 x 204 (200 used), stride 204
//   sGT   [8176,13280)   G chunk transposed: 25 x 204 (200 used), stride 204
//   sXYZ  [13280,13680)  xyz: 4 x 100
// total 13680 floats = 54720 B -> 2 CTAs/SM
// ---------------------------------------------------------------------------
__global__ void __launch_bounds__(256, 2) embed_kernel(
    const float4* __restrict__ imdr,      // (B*NAT*200) float4 (r, r*dx, r*dy, r*dz)
    const int*    __restrict__ tmap,      // (NAT)
    const float4* __restrict__ davg,      // (2*200) float4
    const float4* __restrict__ dstd,
    const float*  __restrict__ type_vector, // (2,4)
    const float*  __restrict__ tW0, const float* __restrict__ tb0,   // (4,8),(8)
    const float*  __restrict__ eW0, const float* __restrict__ eb0,   // (9,25),(25)
    const float*  __restrict__ eW1, const float* __restrict__ eb1,   // (25,50),(50)
    const float*  __restrict__ eW2, const float* __restrict__ eb2)   // (50,100),(100)
{
    extern __shared__ float sm[];
    float* sW0  = sm;
    float* sB0  = sm + 228;
    float* sW1p = sm + 256;
    float* sB1  = sm + 1556;
    float* sW2p = sm + 1608;
    float* sB2  = sm + 7208;
    float* sBias= sm + 7308;
    float* sRiT = sm + 7360;
    float* sGT  = sm + 8176;
    float* sXYZ = sm + 13280;

    int tid = threadIdx.x;
    int a = blockIdx.x;
    int n = a & 1023;
    int t = tmap[n];

    // cooperative weight load + repack (padded rows for aligned float4 reads)
    for (int i = tid; i < 225; i += 256) sW0[i] = eW0[i];
    for (int i = tid; i < 25;  i += 256) sB0[i] = eb0[i];
    for (int i = tid; i < 25 * 52; i += 256) {
        int row = i / 52, m = i - row * 52;
        sW1p[i] = (m < 50) ? eW1[row * 50 + m] : 0.0f;
    }
    for (int i = tid; i < 50;  i += 256) sB1[i] = eb1[i];
    for (int i = tid; i < 50 * 112; i += 256) {
        int k = i / 112, rem = i - k * 112;
        int c = rem / 28, m = rem - c * 28;
        sW2p[i] = (m < 25) ? eW2[k * 100 + c * 25 + m] : 0.0f;
    }
    for (int i = tid; i < 100; i += 256) sB2[i] = eb2[i];
    __syncthreads();

    bool act = (tid < 200);
    float h1[50];
    float ri0 = 0.0f;
    int   nt  = 0;

    if (act) {
        int j = tid;
        nt = (j >= 100) ? 1 : 0;
        float4 im = imdr[(size_t)a * 200 + j];
        float r = im.x;
        float invr = (r > 1e-5f) ? (1.0f / r) : 1.0f;
        float u  = (r - 0.5f) * (1.0f / 5.5f);
        float u2 = u * u;
        float smid = invr * (u * u2 * (-6.0f * u2 + 15.0f * u - 10.0f) + 1.0f);
        float srij = 0.0f;
        if (r > 0.0f && r < 0.5f)        srij = invr;
        else if (r >= 0.5f && r < 6.0f)  srij = smid;
        bool msk = fabsf(r) > 1e-5f;
        float v0 = srij;
        float v1 = msk ? srij * im.y * invr : 0.0f;
        float v2 = msk ? srij * im.z * invr : 0.0f;
        float v3 = msk ? srij * im.w * invr : 0.0f;
        float4 da = davg[t * 200 + j];
        float4 ds = dstd[t * 200 + j];
        v0 = (v0 - da.x) / ds.x;
        v1 = (v1 - da.y) / ds.y;
        v2 = (v2 - da.z) / ds.z;
        v3 = (v3 - da.w) / ds.w;
        sRiT[0 * 204 + j] = v0;
        sRiT[1 * 204 + j] = v1;
        sRiT[2 * 204 + j] = v2;
        sRiT[3 * 204 + j] = v3;
        ri0 = v0;
    } else if (tid >= 200 && tid < 250) {
        // folded layer0 bias on otherwise-idle threads:
        // sBias[t][m] = eb0[m] + sum_k nf_t[k] * eW0[(1+k),m]
        int tt = (tid - 200) / 25, m = (tid - 200) % 25;
        float tv[4];
        #pragma unroll
        for (int p = 0; p < 4; p++) tv[p] = type_vector[tt * 4 + p];
        float bias = sB0[m];
        #pragma unroll
        for (int k = 0; k < 8; k++) {
            float acc = tb0[k];
            #pragma unroll
            for (int p = 0; p < 4; p++) acc += tv[p] * tW0[p * 8 + k];
            float nfk = fast_tanh(acc) + tv[k & 3];
            bias += nfk * sW0[(k + 1) * 25 + m];
        }
        sBias[tt * 25 + m] = bias;
    }
    __syncthreads();

    if (act) {
        // layer0: 1 input (ri0) + folded bias -> 25
        float h0[25];
        #pragma unroll
        for (int m = 0; m < 25; m++)
            h0[m] = fast_tanh(sBias[nt * 25 + m] + ri0 * sW0[m]);

        // layer1: 25 -> 50, resnet += concat[h0,h0]; float4 weight loads
        #pragma unroll
        for (int m = 0; m < 50; m++) h1[m] = sB1[m];
        #pragma unroll 5
        for (int k = 0; k < 25; k++) {
            float hk = h0[k];
            const float4* w4 = (const float4*)(sW1p + k * 52);
            #pragma unroll
            for (int q = 0; q < 12; q++) {
                float4 w = w4[q];
                h1[4 * q + 0] += hk * w.x;
                h1[4 * q + 1] += hk * w.y;
                h1[4 * q + 2] += hk * w.z;
                h1[4 * q + 3] += hk * w.w;
            }
            float2 w2 = *(const float2*)(sW1p + k * 52 + 48);
            h1[48] += hk * w2.x;
            h1[49] += hk * w2.y;
        }
        #pragma unroll
        for (int m = 0; m < 50; m++)
            h1[m] = fast_tanh(h1[m]) + h0[(m < 25) ? m : (m - 25)];
    }

    // layer2 (50 -> 100, resnet += concat[h1,h1]) in four 25-wide chunks,
    // each chunk: compute G^T slice -> xyz partial reduction.
    for (int c = 0; c < 4; c++) {
        if (act) {
            int j = tid;
            float acc[25];
            #pragma unroll
            for (int m = 0; m < 25; m++) acc[m] = sB2[c * 25 + m];
            #pragma unroll 2
            for (int k = 0; k < 50; k++) {
                float hk = h1[k];
                const float4* w4 = (const float4*)(sW2p + k * 112 + c * 28);
                #pragma unroll
                for (int q = 0; q < 6; q++) {
                    float4 w = w4[q];
                    acc[4 * q + 0] += hk * w.x;
                    acc[4 * q + 1] += hk * w.y;
                    acc[4 * q + 2] += hk * w.z;
                    acc[4 * q + 3] += hk * w.w;
                }
                acc[24] += hk * sW2p[k * 112 + c * 28 + 24];
            }
            int roff = (c & 1) * 25;   // resnet index: (c*25+m) mod 50
            #pragma unroll
            for (int m = 0; m < 25; m++)
                sGT[m * 204 + j] = fast_tanh(acc[m]) + h1[roff + m];
        }
        __syncthreads();
        if (tid < 100) {
            int d = tid / 25, mq = tid % 25;
            const float4* rg = (const float4*)(sRiT + d * 204);
            const float4* gg = (const float4*)(sGT + mq * 204);
            float s = 0.0f;
            #pragma unroll 5
            for (int q = 0; q < 50; q++) {
                float4 rv = rg[q];
                float4 gv = gg[q];
                s += rv.x * gv.x + rv.y * gv.y + rv.z * gv.z + rv.w * gv.w;
            }
            sXYZ[d * 100 + c * 25 + mq] = s * (1.0f / 200.0f);
        }
        __syncthreads();
    }

    // DR[m][q] = sum_d xyz[d][m] * xyz[d][q], q < 16
    for (int idx = tid; idx < 1600; idx += 256) {
        int m = idx >> 4, q = idx & 15;
        float s = 0.0f;
        #pragma unroll
        for (int d = 0; d < 4; d++)
            s += sXYZ[d * 100 + m] * sXYZ[d * 100 + q];
        g_DR[(size_t)a * 1600 + idx] = s;
    }
}

// ---------------------------------------------------------------------------
// Kernel 2: fitting net. Block = 4 same-type n's x 4 batches = 16 rows.
// ---------------------------------------------------------------------------
__global__ void __launch_bounds__(256, 1) fit_kernel(
    const int*   __restrict__ tmap,
    const float* __restrict__ fW0, const float* __restrict__ fb0,
    const float* __restrict__ fW1, const float* __restrict__ fb1,
    const float* __restrict__ fW2, const float* __restrict__ fb2,
    const float* __restrict__ fWf, const float* __restrict__ fbf,
    float* __restrict__ out)
{
    extern __shared__ float sm[];
    float* sDR = sm;            // 16*1600
    float* sHa = sDR + 25600;   // 16*240
    float* sHb = sHa + 3840;    // 16*240
    // 33280 floats = 133120 B

    int tid = threadIdx.x;
    int g = blockIdx.x;
    int nn[4];
    nn[0] = g_sorted_n[g * 4 + 0];
    nn[1] = g_sorted_n[g * 4 + 1];
    nn[2] = g_sorted_n[g * 4 + 2];
    nn[3] = g_sorted_n[g * 4 + 3];
    int firstn = (nn[0] >= 0) ? nn[0] : (nn[1] >= 0) ? nn[1]
               : (nn[2] >= 0) ? nn[2] : nn[3];
    if (firstn < 0) return;     // uniform: all-empty padding block
    int t = tmap[firstn];

    for (int idx = tid; idx < 16 * 1600; idx += 256) {
        int row = idx / 1600;
        int k   = idx - row * 1600;
        int b   = row >> 2, s = row & 3;
        int nv  = nn[s];
        sDR[idx] = (nv >= 0) ? g_DR[((size_t)(b * 1024 + nv)) * 1600 + k] : 0.0f;
    }
    __syncthreads();

    int m = tid;
    float acc[16];
    const float* W0 = fW0 + (size_t)t * 1600 * 240;
    const float* W1 = fW1 + t * 240 * 240;
    const float* W2 = fW2 + t * 240 * 240;

    // layer0: 1600 -> 240, no resnet
    if (m < 240) {
        float b0v = fb0[t * 240 + m];
        #pragma unroll
        for (int i = 0; i < 16; i++) acc[i] = b0v;
        for (int k = 0; k < 1600; k += 4) {
            float w0 = W0[(k + 0) * 240 + m];
            float w1 = W0[(k + 1) * 240 + m];
            float w2v = W0[(k + 2) * 240 + m];
            float w3 = W0[(k + 3) * 240 + m];
            #pragma unroll
            for (int i = 0; i < 16; i++) {
                float4 d4 = *(const float4*)&sDR[i * 1600 + k];
                acc[i] += d4.x * w0 + d4.y * w1 + d4.z * w2v + d4.w * w3;
            }
        }
        #pragma unroll
        for (int i = 0; i < 16; i++) sHa[i * 240 + m] = fast_tanh(acc[i]);
    }
    __syncthreads();

    // layer1: 240 -> 240, resnet
    if (m < 240) {
        float b1v = fb1[t * 240 + m];
        #pragma unroll
        for (int i = 0; i < 16; i++) acc[i] = b1v;
        for (int k = 0; k < 240; k += 4) {
            float w0 = W1[(k + 0) * 240 + m];
            float w1 = W1[(k + 1) * 240 + m];
            float w2v = W1[(k + 2) * 240 + m];
            float w3 = W1[(k + 3) * 240 + m];
            #pragma unroll
            for (int i = 0; i < 16; i++) {
                float4 h4 = *(const float4*)&sHa[i * 240 + k];
                acc[i] += h4.x * w0 + h4.y * w1 + h4.z * w2v + h4.w * w3;
            }
        }
        #pragma unroll
        for (int i = 0; i < 16; i++)
            sHb[i * 240 + m] = fast_tanh(acc[i]) + sHa[i * 240 + m];
    }
    __syncthreads();

    // layer2: 240 -> 240, resnet (writes back into sHa; reads of sHa are done)
    if (m < 240) {
        float b2v = fb2[t * 240 + m];
        #pragma unroll
        for (int i = 0; i < 16; i++) acc[i] = b2v;
        for (int k = 0; k < 240; k += 4) {
            float w0 = W2[(k + 0) * 240 + m];
            float w1 = W2[(k + 1) * 240 + m];
            float w2v = W2[(k + 2) * 240 + m];
            float w3 = W2[(k + 3) * 240 + m];
            #pragma unroll
            for (int i = 0; i < 16; i++) {
                float4 h4 = *(const float4*)&sHb[i * 240 + k];
                acc[i] += h4.x * w0 + h4.y * w1 + h4.z * w2v + h4.w * w3;
            }
        }
        #pragma unroll
        for (int i = 0; i < 16; i++)
            sHa[i * 240 + m] = fast_tanh(acc[i]) + sHb[i * 240 + m];
    }
    __syncthreads();

    // final: h @ fWf + fbf
    if (tid < 16) {
        int i = tid, b = i >> 2, s = i & 3;
        int nv = nn[s];
        if (nv >= 0) {
            float e = fbf[t];
            const float* Wf = fWf + t * 240;
            float s0 = 0.0f;
            for (int k = 0; k < 240; k++) s0 += sHa[i * 240 + k] * Wf[k];
            out[4 + b * 1024 + nv] = e + s0;
        }
    }
}

// ---------------------------------------------------------------------------
// Kernel 3: Etot = sum_n Ei (deterministic tree reduce, one block per batch)
// ---------------------------------------------------------------------------
__global__ void etot_kernel(float* __restrict__ out)
{
    __shared__ float red[256];
    int b = blockIdx.x, tid = threadIdx.x;
    float s = 0.0f;
    for (int i = tid; i < 1024; i += 256) s += out[4 + b * 1024 + i];
    red[tid] = s;
    __syncthreads();
    for (int off = 128; off > 0; off >>= 1) {
        if (tid < off) red[tid] += red[tid + off];
        __syncthreads();
    }
    if (tid == 0) out[b] = red[0];
}

// ---------------------------------------------------------------------------
extern "C" void kernel_launch(void* const* d_in, const int* in_sizes, int n_in,
                              void* d_out, int out_size)
{
    // input order: list_neigh, Imagetype_map, type_map, ImageDR, [nghost],
    //              davg, dstd, type_vector, tW0, tb0, eW0, eb0, eW1, eb1,
    //              eW2, eb2, fW0, fb0, fW1, fb1, fW2, fb2, fWf, fbf
    int off = (n_in >= 24) ? 0 : -1;   // nghost scalar may or may not materialize

    const int*    tmap = (const int*)   d_in[1];
    const float4* imdr = (const float4*)d_in[3];
    const float4* davg = (const float4*)d_in[5 + off];
    const float4* dstd = (const float4*)d_in[6 + off];
    const float*  tvec = (const float*) d_in[7 + off];
    const float*  tW0  = (const float*) d_in[8 + off];
    const float*  tb0  = (const float*) d_in[9 + off];
    const float*  eW0  = (const float*) d_in[10 + off];
    const float*  eb0  = (const float*) d_in[11 + off];
    const float*  eW1  = (const float*) d_in[12 + off];
    const float*  eb1  = (const float*) d_in[13 + off];
    const float*  eW2  = (const float*) d_in[14 + off];
    const float*  eb2  = (const float*) d_in[15 + off];
    const float*  fW0  = (const float*) d_in[16 + off];
    const float*  fb0  = (const float*) d_in[17 + off];
    const float*  fW1  = (const float*) d_in[18 + off];
    const float*  fb1  = (const float*) d_in[19 + off];
    const float*  fW2  = (const float*) d_in[20 + off];
    const float*  fb2  = (const float*) d_in[21 + off];
    const float*  fWf  = (const float*) d_in[22 + off];
    const float*  fbf  = (const float*) d_in[23 + off];
    float* out = (float*)d_out;

    cudaFuncSetAttribute(embed_kernel, cudaFuncAttributeMaxDynamicSharedMemorySize, 54720);
    cudaFuncSetAttribute(fit_kernel,   cudaFuncAttributeMaxDynamicSharedMemorySize, 133120);

    sort_kernel<<<1, 1024>>>(tmap);
    embed_kernel<<<4096, 256, 54720>>>(imdr, tmap, davg, dstd, tvec,
                                       tW0, tb0, eW0, eb0, eW1, eb1, eW2, eb2);
    fit_kernel<<<258, 256, 133120>>>(tmap, fW0, fb0, fW1, fb1, fW2, fb2,
                                     fWf, fbf, out);
    etot_kernel<<<4, 256>>>(out);
}

// round 4
// speedup vs baseline: 1.4438x; 1.2797x over previous
#include <cuda_runtime.h>
#include <math.h>

#define BB   4
#define NATN 1024

typedef unsigned long long ull;

// scratch: DR descriptors (B*NAT, 1600) and type-sorted atom list
__device__ float g_DR[(size_t)BB * NATN * 1600];
__device__ int   g_sorted_n[1032];

// ---------------- packed f32x2 helpers (SASS FFMA2) ----------------
__device__ __forceinline__ ull pack2(float lo, float hi)
{
    ull r;
    asm("mov.b64 %0, {%1, %2};" : "=l"(r) : "f"(lo), "f"(hi));
    return r;
}
__device__ __forceinline__ void unpack2(ull v, float& lo, float& hi)
{
    asm("mov.b64 {%0, %1}, %2;" : "=f"(lo), "=f"(hi) : "l"(v));
}
__device__ __forceinline__ ull ffma2(ull a, ull b, ull c)
{
    ull d;
    asm("fma.rn.f32x2 %0, %1, %2, %3;" : "=l"(d) : "l"(a), "l"(b), "l"(c));
    return d;
}

// Branch-free fast tanh: rel err ~1e-6, no overflow for any x.
__device__ __forceinline__ float fast_tanh(float x)
{
    float a = fabsf(x);
    float t = __expf(-2.0f * a);
    float r = __fdividef(1.0f - t, 1.0f + t);
    return copysignf(r, x);
}

// ---------------------------------------------------------------------------
// Kernel 0: deterministic partition of n-indices by atom type (single block)
// ---------------------------------------------------------------------------
__global__ void sort_kernel(const int* __restrict__ tmap)
{
    __shared__ int sa[1024], sb[1024];
    int tid = threadIdx.x;
    int myt = tmap[tid];
    sa[tid] = (myt == 0) ? 1 : 0;
    __syncthreads();
    int* cur = sa; int* nxt = sb;
    for (int off = 1; off < 1024; off <<= 1) {
        int v = cur[tid];
        if (tid >= off) v += cur[tid - off];
        __syncthreads();
        nxt[tid] = v;
        __syncthreads();
        int* tpp = cur; cur = nxt; nxt = tpp;
    }
    int scan0 = cur[tid];
    int cnt0  = cur[1023];

    g_sorted_n[tid] = -1;
    if (tid < 8) g_sorted_n[1024 + tid] = -1;
    __syncthreads();

    if (myt == 0) {
        g_sorted_n[scan0 - 1] = tid;
    } else {
        int base1 = ((cnt0 + 3) >> 2) << 2;
        g_sorted_n[base1 + tid - scan0] = tid;
    }
}

// ---------------------------------------------------------------------------
// Kernel 1: embedding net + xyz + DR. One block = atom. f32x2 mainloops.
// Shared layout (floats):
//   sW0   [0,228)      sB0 [228,256)    sW1p [256,1556) 25x52
//   sB1   [1556,1608)  sW2p[1608,7208)  50 x (4 chunks x 28)
//   sB2p  [7208,7320)  4 x 28 (25 used) sBias[7320,7372)
//   sRiT  [7372,8188)  4 x 204          sGT  [8188,13288) 25 x 204
//   sXYZ  [13288,13688)
// total 13688 floats = 54752 B -> 2 CTAs/SM
// ---------------------------------------------------------------------------
__global__ void __launch_bounds__(256, 2) embed_kernel(
    const float4* __restrict__ imdr,
    const int*    __restrict__ tmap,
    const float4* __restrict__ davg,
    const float4* __restrict__ dstd,
    const float*  __restrict__ type_vector,
    const float*  __restrict__ tW0, const float* __restrict__ tb0,
    const float*  __restrict__ eW0, const float* __restrict__ eb0,
    const float*  __restrict__ eW1, const float* __restrict__ eb1,
    const float*  __restrict__ eW2, const float* __restrict__ eb2)
{
    extern __shared__ float sm[];
    float* sW0  = sm;
    float* sB0  = sm + 228;
    float* sW1p = sm + 256;
    float* sB1  = sm + 1556;
    float* sW2p = sm + 1608;
    float* sB2p = sm + 7208;
    float* sBias= sm + 7320;
    float* sRiT = sm + 7372;
    float* sGT  = sm + 8188;
    float* sXYZ = sm + 13288;

    int tid = threadIdx.x;
    int a = blockIdx.x;
    int n = a & 1023;
    int t = tmap[n];

    for (int i = tid; i < 225; i += 256) sW0[i] = eW0[i];
    for (int i = tid; i < 25;  i += 256) sB0[i] = eb0[i];
    for (int i = tid; i < 25 * 52; i += 256) {
        int row = i / 52, m = i - row * 52;
        sW1p[i] = (m < 50) ? eW1[row * 50 + m] : 0.0f;
    }
    for (int i = tid; i < 50;  i += 256) sB1[i] = eb1[i];
    for (int i = tid; i < 50 * 112; i += 256) {
        int k = i / 112, rem = i - k * 112;
        int c = rem / 28, m = rem - c * 28;
        sW2p[i] = (m < 25) ? eW2[k * 100 + c * 25 + m] : 0.0f;
    }
    for (int i = tid; i < 112; i += 256) {
        int c = i / 28, m = i - c * 28;
        sB2p[i] = (m < 25) ? eb2[c * 25 + m] : 0.0f;
    }
    __syncthreads();

    bool act = (tid < 200);
    float h1[50];
    float ri0 = 0.0f;
    int   nt  = 0;

    if (act) {
        int j = tid;
        nt = (j >= 100) ? 1 : 0;
        float4 im = imdr[(size_t)a * 200 + j];
        float r = im.x;
        float invr = (r > 1e-5f) ? (1.0f / r) : 1.0f;
        float u  = (r - 0.5f) * (1.0f / 5.5f);
        float u2 = u * u;
        float smid = invr * (u * u2 * (-6.0f * u2 + 15.0f * u - 10.0f) + 1.0f);
        float srij = 0.0f;
        if (r > 0.0f && r < 0.5f)        srij = invr;
        else if (r >= 0.5f && r < 6.0f)  srij = smid;
        bool msk = fabsf(r) > 1e-5f;
        float v0 = srij;
        float v1 = msk ? srij * im.y * invr : 0.0f;
        float v2 = msk ? srij * im.z * invr : 0.0f;
        float v3 = msk ? srij * im.w * invr : 0.0f;
        float4 da = davg[t * 200 + j];
        float4 ds = dstd[t * 200 + j];
        v0 = (v0 - da.x) / ds.x;
        v1 = (v1 - da.y) / ds.y;
        v2 = (v2 - da.z) / ds.z;
        v3 = (v3 - da.w) / ds.w;
        sRiT[0 * 204 + j] = v0;
        sRiT[1 * 204 + j] = v1;
        sRiT[2 * 204 + j] = v2;
        sRiT[3 * 204 + j] = v3;
        ri0 = v0;
    } else if (tid >= 200 && tid < 250) {
        // folded layer0 bias: sBias[t][m] = eb0[m] + sum_k nf_t[k]*eW0[1+k][m]
        int tt = (tid - 200) / 25, m = (tid - 200) % 25;
        float tv[4];
        #pragma unroll
        for (int p = 0; p < 4; p++) tv[p] = type_vector[tt * 4 + p];
        float bias = sB0[m];
        #pragma unroll
        for (int k = 0; k < 8; k++) {
            float acc = tb0[k];
            #pragma unroll
            for (int p = 0; p < 4; p++) acc += tv[p] * tW0[p * 8 + k];
            float nfk = fast_tanh(acc) + tv[k & 3];
            bias += nfk * sW0[(k + 1) * 25 + m];
        }
        sBias[tt * 25 + m] = bias;
    }
    __syncthreads();

    if (act) {
        // layer0
        float h0[25];
        #pragma unroll
        for (int m = 0; m < 25; m++)
            h0[m] = fast_tanh(sBias[nt * 25 + m] + ri0 * sW0[m]);

        // layer1: 25 -> 50 with f32x2 accumulators (25 pairs)
        ull h1p[25];
        #pragma unroll
        for (int m = 0; m < 25; m++) h1p[m] = *(const ull*)(sB1 + 2 * m);
        #pragma unroll 5
        for (int k = 0; k < 25; k++) {
            ull hkp = pack2(h0[k], h0[k]);
            const ulonglong2* w2 = (const ulonglong2*)(sW1p + k * 52);
            #pragma unroll
            for (int q = 0; q < 12; q++) {
                ulonglong2 w = w2[q];
                h1p[2 * q]     = ffma2(hkp, w.x, h1p[2 * q]);
                h1p[2 * q + 1] = ffma2(hkp, w.y, h1p[2 * q + 1]);
            }
            ull wl = *(const ull*)(sW1p + k * 52 + 48);
            h1p[24] = ffma2(hkp, wl, h1p[24]);
        }
        #pragma unroll
        for (int m = 0; m < 25; m++) {
            float lo, hi;
            unpack2(h1p[m], lo, hi);
            int i0 = 2 * m, i1 = 2 * m + 1;
            h1[i0] = fast_tanh(lo) + h0[(i0 < 25) ? i0 : (i0 - 25)];
            h1[i1] = fast_tanh(hi) + h0[(i1 < 25) ? i1 : (i1 - 25)];
        }
    }

    // layer2 (50 -> 100) in four 25-wide chunks; f32x2 accumulators
    for (int c = 0; c < 4; c++) {
        if (act) {
            int j = tid;
            ull accp[12];
            #pragma unroll
            for (int q = 0; q < 12; q++)
                accp[q] = *(const ull*)(sB2p + c * 28 + 2 * q);
            float acc24 = sB2p[c * 28 + 24];
            #pragma unroll 2
            for (int k = 0; k < 50; k++) {
                float hk = h1[k];
                ull hkp = pack2(hk, hk);
                const float* wrow = sW2p + k * 112 + c * 28;
                const ulonglong2* w4 = (const ulonglong2*)wrow;
                #pragma unroll
                for (int q = 0; q < 6; q++) {
                    ulonglong2 w = w4[q];
                    accp[2 * q]     = ffma2(hkp, w.x, accp[2 * q]);
                    accp[2 * q + 1] = ffma2(hkp, w.y, accp[2 * q + 1]);
                }
                acc24 += hk * wrow[24];
            }
            int roff = (c & 1) * 25;
            #pragma unroll
            for (int q = 0; q < 12; q++) {
                float lo, hi;
                unpack2(accp[q], lo, hi);
                sGT[(2 * q)     * 204 + j] = fast_tanh(lo) + h1[roff + 2 * q];
                sGT[(2 * q + 1) * 204 + j] = fast_tanh(hi) + h1[roff + 2 * q + 1];
            }
            sGT[24 * 204 + j] = fast_tanh(acc24) + h1[roff + 24];
        }
        __syncthreads();
        if (tid < 100) {
            int d = tid / 25, mq = tid % 25;
            const ulonglong2* rg = (const ulonglong2*)(sRiT + d * 204);
            const ulonglong2* gg = (const ulonglong2*)(sGT + mq * 204);
            ull accp = pack2(0.0f, 0.0f);
            #pragma unroll 5
            for (int q = 0; q < 50; q++) {
                ulonglong2 rv = rg[q];
                ulonglong2 gv = gg[q];
                accp = ffma2(rv.x, gv.x, accp);
                accp = ffma2(rv.y, gv.y, accp);
            }
            float lo, hi;
            unpack2(accp, lo, hi);
            sXYZ[d * 100 + c * 25 + mq] = (lo + hi) * (1.0f / 200.0f);
        }
        __syncthreads();
    }

    // DR[m][q] = sum_d xyz[d][m] * xyz[d][q], q < 16
    for (int idx = tid; idx < 1600; idx += 256) {
        int m = idx >> 4, q = idx & 15;
        float s = 0.0f;
        #pragma unroll
        for (int d = 0; d < 4; d++)
            s += sXYZ[d * 100 + m] * sXYZ[d * 100 + q];
        g_DR[(size_t)a * 1600 + idx] = s;
    }
}

// ---------------------------------------------------------------------------
// Kernel 2: fitting net, f32x2 over row pairs. Block = 16 rows (4 n x 4 b).
// Shared: sDR2 row-pair interleaved [8][1600*2] = 25600 floats,
//         sHa2 [8][240*2] = 3840 at 25600, sHb2 3840 at 29440. 133120 B.
// ---------------------------------------------------------------------------
__global__ void __launch_bounds__(256, 1) fit_kernel(
    const int*   __restrict__ tmap,
    const float* __restrict__ fW0, const float* __restrict__ fb0,
    const float* __restrict__ fW1, const float* __restrict__ fb1,
    const float* __restrict__ fW2, const float* __restrict__ fb2,
    const float* __restrict__ fWf, const float* __restrict__ fbf,
    float* __restrict__ out)
{
    extern __shared__ float sm[];
    float* sDR2 = sm;            // pair p: [p*3200 + 2k + parity]
    float* sHa2 = sm + 25600;    // pair p: [p*480 + 2k + parity]
    float* sHb2 = sm + 29440;

    int tid = threadIdx.x;
    int g = blockIdx.x;
    int nn[4];
    nn[0] = g_sorted_n[g * 4 + 0];
    nn[1] = g_sorted_n[g * 4 + 1];
    nn[2] = g_sorted_n[g * 4 + 2];
    nn[3] = g_sorted_n[g * 4 + 3];
    int firstn = (nn[0] >= 0) ? nn[0] : (nn[1] >= 0) ? nn[1]
               : (nn[2] >= 0) ? nn[2] : nn[3];
    if (firstn < 0) return;
    int t = tmap[firstn];

    // stage DR row-pair interleaved
    for (int idx = tid; idx < 16 * 1600; idx += 256) {
        int row = idx / 1600;
        int k   = idx - row * 1600;
        int b   = row >> 2, s = row & 3;
        int nv  = nn[s];
        float v = (nv >= 0) ? g_DR[((size_t)(b * 1024 + nv)) * 1600 + k] : 0.0f;
        sDR2[(row >> 1) * 3200 + 2 * k + (row & 1)] = v;
    }
    __syncthreads();

    int m = tid;
    const float* W0 = fW0 + (size_t)t * 1600 * 240;
    const float* W1 = fW1 + t * 240 * 240;
    const float* W2 = fW2 + t * 240 * 240;

    ull  accp[8];
    float prevA[16];   // layer activations kept in registers for resnet
    float prevB[16];

    // layer0: 1600 -> 240
    if (m < 240) {
        float b0v = fb0[t * 240 + m];
        ull b0p = pack2(b0v, b0v);
        #pragma unroll
        for (int p = 0; p < 8; p++) accp[p] = b0p;
        for (int k = 0; k < 1600; k += 4) {
            float w0 = W0[(k + 0) * 240 + m];
            float w1 = W0[(k + 1) * 240 + m];
            float w2v = W0[(k + 2) * 240 + m];
            float w3 = W0[(k + 3) * 240 + m];
            ull wp0 = pack2(w0, w0), wp1 = pack2(w1, w1);
            ull wp2 = pack2(w2v, w2v), wp3 = pack2(w3, w3);
            #pragma unroll
            for (int p = 0; p < 8; p++) {
                const ulonglong2* dd = (const ulonglong2*)(sDR2 + p * 3200 + 2 * k);
                ulonglong2 dA = dd[0];
                ulonglong2 dB = dd[1];
                accp[p] = ffma2(dA.x, wp0, accp[p]);
                accp[p] = ffma2(dA.y, wp1, accp[p]);
                accp[p] = ffma2(dB.x, wp2, accp[p]);
                accp[p] = ffma2(dB.y, wp3, accp[p]);
            }
        }
        #pragma unroll
        for (int p = 0; p < 8; p++) {
            float lo, hi;
            unpack2(accp[p], lo, hi);
            float a0 = fast_tanh(lo), a1 = fast_tanh(hi);
            prevA[2 * p] = a0; prevA[2 * p + 1] = a1;
            *(ull*)(sHa2 + p * 480 + 2 * m) = pack2(a0, a1);
        }
    }
    __syncthreads();

    // layer1: 240 -> 240, resnet
    if (m < 240) {
        float b1v = fb1[t * 240 + m];
        ull b1p = pack2(b1v, b1v);
        #pragma unroll
        for (int p = 0; p < 8; p++) accp[p] = b1p;
        for (int k = 0; k < 240; k += 4) {
            float w0 = W1[(k + 0) * 240 + m];
            float w1 = W1[(k + 1) * 240 + m];
            float w2v = W1[(k + 2) * 240 + m];
            float w3 = W1[(k + 3) * 240 + m];
            ull wp0 = pack2(w0, w0), wp1 = pack2(w1, w1);
            ull wp2 = pack2(w2v, w2v), wp3 = pack2(w3, w3);
            #pragma unroll
            for (int p = 0; p < 8; p++) {
                const ulonglong2* hh = (const ulonglong2*)(sHa2 + p * 480 + 2 * k);
                ulonglong2 hA = hh[0];
                ulonglong2 hB = hh[1];
                accp[p] = ffma2(hA.x, wp0, accp[p]);
                accp[p] = ffma2(hA.y, wp1, accp[p]);
                accp[p] = ffma2(hB.x, wp2, accp[p]);
                accp[p] = ffma2(hB.y, wp3, accp[p]);
            }
        }
        #pragma unroll
        for (int p = 0; p < 8; p++) {
            float lo, hi;
            unpack2(accp[p], lo, hi);
            float a0 = fast_tanh(lo) + prevA[2 * p];
            float a1 = fast_tanh(hi) + prevA[2 * p + 1];
            prevB[2 * p] = a0; prevB[2 * p + 1] = a1;
            *(ull*)(sHb2 + p * 480 + 2 * m) = pack2(a0, a1);
        }
    }
    __syncthreads();

    // layer2: 240 -> 240, resnet; result into sHa2 (its reads are done)
    if (m < 240) {
        float b2v = fb2[t * 240 + m];
        ull b2p = pack2(b2v, b2v);
        #pragma unroll
        for (int p = 0; p < 8; p++) accp[p] = b2p;
        for (int k = 0; k < 240; k += 4) {
            float w0 = W2[(k + 0) * 240 + m];
            float w1 = W2[(k + 1) * 240 + m];
            float w2v = W2[(k + 2) * 240 + m];
            float w3 = W2[(k + 3) * 240 + m];
            ull wp0 = pack2(w0, w0), wp1 = pack2(w1, w1);
            ull wp2 = pack2(w2v, w2v), wp3 = pack2(w3, w3);
            #pragma unroll
            for (int p = 0; p < 8; p++) {
                const ulonglong2* hh = (const ulonglong2*)(sHb2 + p * 480 + 2 * k);
                ulonglong2 hA = hh[0];
                ulonglong2 hB = hh[1];
                accp[p] = ffma2(hA.x, wp0, accp[p]);
                accp[p] = ffma2(hA.y, wp1, accp[p]);
                accp[p] = ffma2(hB.x, wp2, accp[p]);
                accp[p] = ffma2(hB.y, wp3, accp[p]);
            }
        }
        #pragma unroll
        for (int p = 0; p < 8; p++) {
            float lo, hi;
            unpack2(accp[p], lo, hi);
            float a0 = fast_tanh(lo) + prevB[2 * p];
            float a1 = fast_tanh(hi) + prevB[2 * p + 1];
            *(ull*)(sHa2 + p * 480 + 2 * m) = pack2(a0, a1);
        }
    }
    __syncthreads();

    // final: h @ fWf + fbf
    if (tid < 16) {
        int i = tid, b = i >> 2, s = i & 3;
        int nv = nn[s];
        if (nv >= 0) {
            int p = i >> 1, par = i & 1;
            float e = fbf[t];
            const float* Wf = fWf + t * 240;
            float s0 = 0.0f;
            for (int k = 0; k < 240; k++)
                s0 += sHa2[p * 480 + 2 * k + par] * Wf[k];
            out[4 + b * 1024 + nv] = e + s0;
        }
    }
}

// ---------------------------------------------------------------------------
// Kernel 3: Etot = sum_n Ei (deterministic tree reduce, one block per batch)
// ---------------------------------------------------------------------------
__global__ void etot_kernel(float* __restrict__ out)
{
    __shared__ float red[256];
    int b = blockIdx.x, tid = threadIdx.x;
    float s = 0.0f;
    for (int i = tid; i < 1024; i += 256) s += out[4 + b * 1024 + i];
    red[tid] = s;
    __syncthreads();
    for (int off = 128; off > 0; off >>= 1) {
        if (tid < off) red[tid] += red[tid + off];
        __syncthreads();
    }
    if (tid == 0) out[b] = red[0];
}

// ---------------------------------------------------------------------------
extern "C" void kernel_launch(void* const* d_in, const int* in_sizes, int n_in,
                              void* d_out, int out_size)
{
    int off = (n_in >= 24) ? 0 : -1;   // nghost scalar may or may not materialize

    const int*    tmap = (const int*)   d_in[1];
    const float4* imdr = (const float4*)d_in[3];
    const float4* davg = (const float4*)d_in[5 + off];
    const float4* dstd = (const float4*)d_in[6 + off];
    const float*  tvec = (const float*) d_in[7 + off];
    const float*  tW0  = (const float*) d_in[8 + off];
    const float*  tb0  = (const float*) d_in[9 + off];
    const float*  eW0  = (const float*) d_in[10 + off];
    const float*  eb0  = (const float*) d_in[11 + off];
    const float*  eW1  = (const float*) d_in[12 + off];
    const float*  eb1  = (const float*) d_in[13 + off];
    const float*  eW2  = (const float*) d_in[14 + off];
    const float*  eb2  = (const float*) d_in[15 + off];
    const float*  fW0  = (const float*) d_in[16 + off];
    const float*  fb0  = (const float*) d_in[17 + off];
    const float*  fW1  = (const float*) d_in[18 + off];
    const float*  fb1  = (const float*) d_in[19 + off];
    const float*  fW2  = (const float*) d_in[20 + off];
    const float*  fb2  = (const float*) d_in[21 + off];
    const float*  fWf  = (const float*) d_in[22 + off];
    const float*  fbf  = (const float*) d_in[23 + off];
    float* out = (float*)d_out;

    cudaFuncSetAttribute(embed_kernel, cudaFuncAttributeMaxDynamicSharedMemorySize, 54752);
    cudaFuncSetAttribute(fit_kernel,   cudaFuncAttributeMaxDynamicSharedMemorySize, 133120);

    sort_kernel<<<1, 1024>>>(tmap);
    embed_kernel<<<4096, 256, 54752>>>(imdr, tmap, davg, dstd, tvec,
                                       tW0, tb0, eW0, eb0, eW1, eb1, eW2, eb2);
    fit_kernel<<<258, 256, 133120>>>(tmap, fW0, fb0, fW1, fb1, fW2, fb2,
                                     fWf, fbf, out);
    etot_kernel<<<4, 256>>>(out);
}